// round 14
// baseline (speedup 1.0000x reference)
#include <cuda_runtime.h>
#include <math.h>
#include <cstdint>
#include <mma.h>

using namespace nvcuda;

#define NROW 16384
#define DD 64
#define BM 64
#define BK 32
#define NT (NROW / BK)              // 512 k-chunks
#define STAGES 4
#define LDA 40                      // A tile row stride (floats), padded
#define LDB 72                      // B tile row stride (floats), padded
#define LDE 68                      // epilogue stage stride (floats)
#define A_BYTES (BM * LDA * 4)      // 10240
#define B_BYTES (BK * LDB * 4)      // 9216
#define STAGE_BYTES (A_BYTES + B_BYTES)   // 19456
#define SMEM_TOTAL (STAGES * STAGE_BYTES) // 77824  -> 2 CTAs/SM

// scratch: T = logmap0(hyp_linear(h)), row-major [16384][64], col 0 = 1.0 (rowsum trick)
__device__ __align__(256) float g_T[(size_t)NROW * DD];

__device__ __forceinline__ void cp16(uint32_t dst, const void* src) {
    asm volatile("cp.async.cg.shared.global [%0], [%1], 16;" :: "r"(dst), "l"(src));
}
#define CP_COMMIT() asm volatile("cp.async.commit_group;" ::: "memory")
#define CP_WAIT2()  asm volatile("cp.async.wait_group 2;" ::: "memory")
#define CP_WAIT0()  asm volatile("cp.async.wait_group 0;" ::: "memory")

__device__ __forceinline__ uint32_t smem_u32(const void* p) {
    uint32_t a;
    asm("{ .reg .u64 t; cvta.to.shared.u64 t, %1; cvt.u32.u64 %0, t; }" : "=r"(a) : "l"(p));
    return a;
}

// ---------------------------------------------------------------------------
// Kernel A: per-row T[r][:] = logmap0( hyp_linear(point) ),  T[r][0] = 1.0
// ---------------------------------------------------------------------------
__global__ void __launch_bounds__(256) klinear(
    const float* __restrict__ in, const float* __restrict__ W,
    const float* __restrict__ b, int raw)
{
    __shared__ float Ws[DD * DD];
    __shared__ float ub[DD];

    for (int i = threadIdx.x; i < DD * DD; i += 256) Ws[i] = W[i];
    if (threadIdx.x == 0) {
        float bn2 = 0.f;
        for (int j = 1; j < DD; j++) bn2 += b[j] * b[j];
        float bn = fmaxf(sqrtf(bn2), 1e-15f);
        float sb = sinhf(bn) / bn;
        float h2 = 0.f;
        for (int j = 1; j < DD; j++) { float t = sb * b[j]; h2 += t * t; }
        float hb0 = sqrtf(fmaxf(1.f + h2, 1e-7f));
        float un  = fmaxf(sqrtf(h2), 1e-15f);
        float cb  = acoshf(fmaxf(hb0, 1.f + 1e-7f)) / un;
        ub[0] = 0.f;
        for (int j = 1; j < DD; j++) ub[j] = cb * (sb * b[j]);
    }
    __syncthreads();

    const int r = blockIdx.x * 256 + threadIdx.x;
    const float* row = in + (size_t)r * DD;

    float p[DD]; float p0;
    if (raw) {
        float n2 = 0.f;
#pragma unroll
        for (int j = 1; j < DD; j++) { p[j] = row[j]; n2 += p[j] * p[j]; }
        float xn = fmaxf(sqrtf(n2), 1e-15f);
        float s  = sinhf(xn) / xn;
        float t2 = 0.f;
#pragma unroll
        for (int j = 1; j < DD; j++) { p[j] = s * p[j]; t2 += p[j] * p[j]; }
        p0 = sqrtf(fmaxf(1.f + t2, 1e-7f));
    } else {
        p0 = row[0];
#pragma unroll
        for (int j = 1; j < DD; j++) p[j] = row[j];
    }

    // u = logmap0(p) tail
    float yn2 = 0.f;
#pragma unroll
    for (int j = 1; j < DD; j++) yn2 += p[j] * p[j];
    float yn = fmaxf(sqrtf(yn2), 1e-15f);
    float cl = acoshf(fmaxf(p0, 1.f + 1e-7f)) / yn;
    float u[DD];
#pragma unroll
    for (int j = 1; j < DD; j++) u[j] = cl * p[j];

    // v = u @ W^T (tail)
    float v[DD];
#pragma unroll 2
    for (int j = 1; j < DD; j++) {
        const float* wr = &Ws[j * DD];
        float a0 = 0.f, a1 = 0.f;
#pragma unroll
        for (int k = 1; k < DD; k += 2) {
            a0 = fmaf(u[k], wr[k], a0);
            if (k + 1 < DD) a1 = fmaf(u[k + 1], wr[k + 1], a1);
        }
        v[j] = a0 + a1;
    }

    // res = proj(expmap0(v))
    float vn2 = 0.f;
#pragma unroll
    for (int j = 1; j < DD; j++) vn2 += v[j] * v[j];
    float vn = fmaxf(sqrtf(vn2), 1e-15f);
    float se = sinhf(vn) / vn;
    float rt2 = 0.f;
#pragma unroll
    for (int j = 1; j < DD; j++) { v[j] = se * v[j]; rt2 += v[j] * v[j]; }
    float r0 = sqrtf(fmaxf(1.f + rt2, 1e-7f));

    // mobius_add(res, hyp_bias)
    float ynb = fmaxf(sqrtf(rt2), 1e-15f);
    float alpha = 0.f;
#pragma unroll
    for (int j = 1; j < DD; j++) alpha += (v[j] / ynb) * ub[j];
    float cf = alpha * (1.f - r0);
    float w[DD];
    float ux = 0.f, sw2 = 0.f;
#pragma unroll
    for (int j = 1; j < DD; j++) {
        w[j] = ub[j] - cf * (v[j] / ynb);
        ux  += v[j] * w[j];
        sw2 += w[j] * w[j];
    }
    float v20   = ux / fmaxf(r0, 1e-7f);
    float md    = sw2 - v20 * v20;
    float normu = fminf(sqrtf(fmaxf(md, 1e-7f)), 1e6f);
    float theta = fmaxf(normu, 1e-15f);
    float chv   = coshf(theta);
    float scl   = sinhf(theta) / theta;
    float so2 = 0.f;
#pragma unroll
    for (int j = 1; j < DD; j++) { v[j] = chv * v[j] + scl * w[j]; so2 += v[j] * v[j]; }
    float o0 = sqrtf(fmaxf(1.f + so2, 1e-7f));

    // T row = logmap0(out);  T[r][0] = 1.0
    float tn = fmaxf(sqrtf(so2), 1e-15f);
    float c3 = acoshf(fmaxf(o0, 1.f + 1e-7f)) / tn;
    float* To = g_T + (size_t)r * DD;
    To[0] = 1.0f;
#pragma unroll
    for (int j = 1; j < DD; j++) To[j] = c3 * v[j];
}

// ---------------------------------------------------------------------------
// Kernel G: Z = adj_tile(64 x 16384) @ T (16384 x 64) via tf32 WMMA.
// CUTLASS-multistage pipeline: ONE barrier per iteration. Prologue fills
// STAGES-1 stages; at iter t: wait stage t%S landed -> sync -> refill the
// stage freed at t-1 with chunk t+S-1 -> compute stage t%S.
// 2 CTAs/SM, fused hyperbolic epilogue. Z[:,0] = rowsum (T col 0 == 1).
// ---------------------------------------------------------------------------
__global__ void __launch_bounds__(256, 2) kagg(
    const float* __restrict__ adj, float* __restrict__ out)
{
    extern __shared__ char smem[];
    const uint32_t sbase = smem_u32(smem);
    const int tid = threadIdx.x;
    const int wid = tid >> 5;
    const int wr = wid & 3;          // warp row group (16 rows each)
    const int wc = wid >> 2;         // warp col group (32 cols each)
    const int rbase = blockIdx.x * BM;

    // per-thread 4 cp.async chunks per stage (1024 x 16B)
    uint32_t soff[4];
    const float* gp[4];
    int step[4];
#pragma unroll
    for (int i = 0; i < 4; i++) {
        int c = tid + i * 256;
        if (c < 512) {                             // A: 64 rows x 8 chunks of 16B
            int row = c >> 3, q = c & 7;
            soff[i] = row * (LDA * 4) + q * 16;
            gp[i]   = adj + (size_t)(rbase + row) * NROW + q * 4;
            step[i] = BK;
        } else {                                   // B: 32 rows x 16 chunks of 16B
            int c2 = c - 512;
            int k = c2 >> 4, q = c2 & 15;
            soff[i] = A_BYTES + k * (LDB * 4) + q * 16;
            gp[i]   = g_T + (size_t)k * DD + q * 4;
            step[i] = BK * DD;
        }
    }

    // prologue: fill stages 0..STAGES-2 (chunks 0..STAGES-2)
#pragma unroll
    for (int t = 0; t < STAGES - 1; t++) {
        uint32_t sb = sbase + t * STAGE_BYTES;
#pragma unroll
        for (int i = 0; i < 4; i++) cp16(sb + soff[i], gp[i] + (size_t)t * step[i]);
        CP_COMMIT();
    }

    wmma::fragment<wmma::accumulator, 16, 16, 8, float> acc[2];
#pragma unroll
    for (int j = 0; j < 2; j++) wmma::fill_fragment(acc[j], 0.0f);

    for (int t = 0; t < NT; t++) {
        const int s = t % STAGES;
        CP_WAIT2();                 // chunk t landed (keep <=2 groups in flight)
        __syncthreads();            // all warps done with iter t-1's stage

        // refill the stage freed at iter t-1 with chunk t+STAGES-1
        {
            int fc = t + STAGES - 1;
            if (fc < NT) {
                const int fs = (t + STAGES - 1) % STAGES;
                uint32_t sb = sbase + fs * STAGE_BYTES;
#pragma unroll
                for (int i = 0; i < 4; i++) cp16(sb + soff[i], gp[i] + (size_t)fc * step[i]);
            }
            CP_COMMIT();            // empty group in the tail keeps accounting aligned
        }

        const float* As = (const float*)(smem + s * STAGE_BYTES);
        const float* Bs = (const float*)(smem + s * STAGE_BYTES + A_BYTES);

#pragma unroll
        for (int kk = 0; kk < BK / 8; kk++) {
            wmma::fragment<wmma::matrix_a, 16, 16, 8, wmma::precision::tf32, wmma::row_major> a0;
            wmma::fragment<wmma::matrix_b, 16, 16, 8, wmma::precision::tf32, wmma::row_major> b0, b1;
            wmma::load_matrix_sync(a0, As + (wr * 16) * LDA + kk * 8, LDA);
            wmma::load_matrix_sync(b0, Bs + (kk * 8) * LDB + wc * 32, LDB);
            wmma::load_matrix_sync(b1, Bs + (kk * 8) * LDB + wc * 32 + 16, LDB);
            wmma::mma_sync(acc[0], a0, b0, acc[0]);
            wmma::mma_sync(acc[1], a0, b1, acc[1]);
        }
    }
    CP_WAIT0();
    __syncthreads();

    // stage Z into smem (row stride LDE)
    float* E = (float*)smem;
#pragma unroll
    for (int j = 0; j < 2; j++)
        wmma::store_matrix_sync(&E[(wr * 16) * LDE + wc * 32 + j * 16],
                                acc[j], LDE, wmma::mem_row_major);
    __syncthreads();

    // epilogue: one thread per row
    if (tid < BM) {
        float z[DD];
#pragma unroll
        for (int j = 0; j < DD; j++) z[j] = E[tid * LDE + j];

        float s0 = z[0];                              // rowsum (T col 0 == 1)
        float rinv = (s0 != 0.f) ? (1.f / s0) : 0.f;
        float zn2 = 0.f;
#pragma unroll
        for (int j = 1; j < DD; j++) { z[j] = rinv * z[j]; zn2 += z[j] * z[j]; }
        // agg = proj(expmap0(zt))
        float xn = fmaxf(sqrtf(zn2), 1e-15f);
        float sg = sinhf(xn) / xn;
        float a2 = 0.f;
#pragma unroll
        for (int j = 1; j < DD; j++) { z[j] = sg * z[j]; a2 += z[j] * z[j]; }
        float a0 = sqrtf(fmaxf(1.f + a2, 1e-7f));
        // hyp_act: relu(logmap0(agg)) -> expmap0 -> proj
        float ynA = fmaxf(sqrtf(a2), 1e-15f);
        float clA = acoshf(fmaxf(a0, 1.f + 1e-7f)) / ynA;
        float rn2 = 0.f;
#pragma unroll
        for (int j = 1; j < DD; j++) { z[j] = fmaxf(clA * z[j], 0.f); rn2 += z[j] * z[j]; }
        float rn = fmaxf(sqrtf(rn2), 1e-15f);
        float sh = sinhf(rn) / rn;
        float h2s = 0.f;
#pragma unroll
        for (int j = 1; j < DD; j++) { z[j] = sh * z[j]; h2s += z[j] * z[j]; }
        float h0 = sqrtf(fmaxf(1.f + h2s, 1e-7f));

        float* orow = out + (size_t)(rbase + tid) * DD;
        orow[0] = h0;
#pragma unroll
        for (int j = 1; j < DD; j++) orow[j] = z[j];
    }
}

// ---------------------------------------------------------------------------
extern "C" void kernel_launch(void* const* d_in, const int* in_sizes, int n_in,
                              void* d_out, int out_size) {
    (void)in_sizes; (void)n_in; (void)out_size;
    const float* x   = (const float*)d_in[0];
    const float* adj = (const float*)d_in[1];
    const float* W1  = (const float*)d_in[2];
    const float* b1  = (const float*)d_in[3];
    const float* W2  = (const float*)d_in[4];
    const float* b2  = (const float*)d_in[5];

    float* out = (float*)d_out;
    float* h1 = out;
    float* h2 = out + (size_t)NROW * DD;

    cudaFuncSetAttribute(kagg, cudaFuncAttributeMaxDynamicSharedMemorySize, SMEM_TOTAL);

    klinear<<<NROW / 256, 256>>>(x, W1, b1, 1);
    kagg<<<NROW / BM, 256, SMEM_TOTAL>>>(adj, h1);
    klinear<<<NROW / 256, 256>>>(h1, W2, b2, 0);
    kagg<<<NROW / BM, 256, SMEM_TOTAL>>>(adj, h2);
}